// round 9
// baseline (speedup 1.0000x reference)
#include <cuda_runtime.h>

typedef unsigned long long u64;

#define MAXN 100000
#define MAXE 1600000
#define D    128
#define SCAN_BS 512
#define MAX_SCAN_BLOCKS 256

#define GT 128                          // GEMM rows per CTA
#define AST2 129                        // As2 row stride in u64
#define A2_BYTES (128 * AST2 * 8)       // 132096
#define W_BYTES  (128 * 128 * 4)        // 65536
#define GEMM_SMEM (A2_BYTES + W_BYTES)  // 197632 (< 227KB cap)

// ---------------- scratch (device globals; fully rewritten each launch) ----
__device__ __align__(16) float g_dis[MAXN];
__device__ __align__(16) float g_xw [(size_t)MAXN * D];
__device__ __align__(16) float g_h  [(size_t)MAXN * D];
__device__ int   g_cnt[MAXN];
__device__ int   g_incl[MAXN];
__device__ int   g_bsum[MAX_SCAN_BLOCKS];
__device__ int   g_rowstart[MAXN + 1];
__device__ int   g_cursor[MAXN];
__device__ __align__(8) int   g_csr_src[MAXE];
__device__ __align__(8) float g_csr_coef[MAXE];
__device__ int g_is64;

// ---------------- edge dtype detection -------------------------------------
__global__ void k_detect(const int* __restrict__ e32, int nwords) {
    __shared__ int any;
    if (threadIdx.x == 0) any = 0;
    __syncthreads();
    int lim = nwords < 4096 ? nwords : 4096;
    for (int w = 1 + 2 * threadIdx.x; w < lim; w += 2 * blockDim.x)
        if (e32[w] != 0) any = 1;
    __syncthreads();
    if (threadIdx.x == 0) g_is64 = any ? 0 : 1;
}
__device__ __forceinline__ int edge_src(const int* e, int E, int i) {
    return g_is64 ? e[2 * (size_t)i] : e[i];
}
__device__ __forceinline__ int edge_dst(const int* e, int E, int i) {
    return g_is64 ? e[2 * ((size_t)E + i)] : e[(size_t)E + i];
}

// ---------------- zero (split so GEMM1 is the 4th launch for ncu) ----------
__global__ void k_zero_cnt(int n) {
    int i = blockIdx.x * blockDim.x + threadIdx.x;
    if (i < n) g_cnt[i] = 0;
}
__global__ void k_zero_cur(int n) {
    int i = blockIdx.x * blockDim.x + threadIdx.x;
    if (i < n) g_cursor[i] = 0;
}

// ---------------- CSR build -------------------------------------------------
__global__ void k_scan_block(int n) {
    __shared__ int sh[SCAN_BS];
    int i = blockIdx.x * SCAN_BS + threadIdx.x;
    int v = (i < n) ? g_cnt[i] : 0;
    if (i < n) g_dis[i] = rsqrtf((float)v + 1.0f);
    sh[threadIdx.x] = v;
    __syncthreads();
    #pragma unroll
    for (int off = 1; off < SCAN_BS; off <<= 1) {
        int t = (threadIdx.x >= off) ? sh[threadIdx.x - off] : 0;
        __syncthreads();
        sh[threadIdx.x] += t;
        __syncthreads();
    }
    if (i < n) g_incl[i] = sh[threadIdx.x];
    if (threadIdx.x == SCAN_BS - 1) g_bsum[blockIdx.x] = sh[threadIdx.x];
}
__global__ void k_scan_tops(int nblocks) {
    __shared__ int sh[MAX_SCAN_BLOCKS];
    int v = (threadIdx.x < nblocks) ? g_bsum[threadIdx.x] : 0;
    sh[threadIdx.x] = v;
    __syncthreads();
    #pragma unroll
    for (int off = 1; off < MAX_SCAN_BLOCKS; off <<= 1) {
        int t = (threadIdx.x >= off) ? sh[threadIdx.x - off] : 0;
        __syncthreads();
        sh[threadIdx.x] += t;
        __syncthreads();
    }
    g_bsum[threadIdx.x] = sh[threadIdx.x] - v;
}
__global__ void k_scan_add(int n, int E) {
    int i = blockIdx.x * SCAN_BS + threadIdx.x;
    if (i < n) {
        int excl = g_incl[i] - g_cnt[i] + g_bsum[blockIdx.x];
        g_rowstart[i] = excl;
        if (i == n - 1) g_rowstart[n] = excl + g_cnt[i];
    }
}
__global__ void k_fill(const int* __restrict__ edge, int E) {
    int i = blockIdx.x * blockDim.x + threadIdx.x;
    if (i < E) {
        int s = edge_src(edge, E, i);
        int d = edge_dst(edge, E, i);
        int pos = g_rowstart[d] + atomicAdd(&g_cursor[d], 1);
        g_csr_src[pos]  = s;
        g_csr_coef[pos] = g_dis[s] * g_dis[d];
    }
}

// ---------------- f32x2 helpers ---------------------------------------------
union F2U { float2 f; u64 u; };
__device__ __forceinline__ u64 dup_f32x2(float x) {
    F2U t; t.f = make_float2(x, x); return t.u;
}
__device__ __forceinline__ void ffma2(u64& acc, u64 a, u64 w) {
    asm("fma.rn.f32x2 %0, %1, %2, %0;" : "+l"(acc) : "l"(a), "l"(w));
}

// ---------------- packed-fp32 GEMM (pre-dup A, col-pair FFMA2) --------------
// out = f(A @ W + bias). Exact fp32 via fma.rn.f32x2.
// Block: 128 rows x 128 cols x K=128, 512 threads (16 warps, 4/SMSP).
// Thread: 4 rows x 8 cols (4 col-pair accs per row).
//   A in smem pre-duplicated: As2[k][r] = (A[r][k], A[r][k])  -> LDS.64,
//   W pairs natural from row-major LDS.128 halves. Zero dup MOVs in loop.
// Per k/thread: 4 LDS.64 + 2 LDS.128 + 16 FFMA2 = 22 issues (73% fma).
__global__ void __launch_bounds__(512, 1)
k_gemm_p(const float* __restrict__ A, int n,
         const float* __restrict__ W, const float* __restrict__ bias,
         int relu, float* __restrict__ out,
         const int* __restrict__ edge, int E, int hist)
{
    extern __shared__ __align__(16) char smem[];
    u64*   As2 = (u64*)smem;                   // [k=128][AST2]
    float* Ws  = (float*)(smem + A2_BYTES);    // [128][128]

    const int tid = threadIdx.x;
    const int rowBlock = blockIdx.x * GT;

    // -- folded degree histogram (fire-and-forget REDs under FMA-bound) -----
    if (hist) {
        int per  = (E + gridDim.x - 1) / gridDim.x;
        int base = blockIdx.x * per;
        int lim  = base + per; if (lim > E) lim = E;
        for (int i = base + tid; i < lim; i += 512)
            atomicAdd(&g_cnt[edge_dst(edge, E, i)], 1);
    }

    // -- fill A transposed + duplicated: As2[k][r] = (a,a) -------------------
    #pragma unroll
    for (int i = 0; i < 8; i++) {
        int idx = tid + i * 512;       // 0..4095: (r, c4)
        int r   = idx >> 5;
        int c4  = idx & 31;
        int grow = rowBlock + r;
        float4 v = make_float4(0.f, 0.f, 0.f, 0.f);
        if (grow < n) v = ((const float4*)(A + (size_t)grow * D))[c4];
        int k0 = c4 * 4;
        As2[(k0 + 0) * AST2 + r] = dup_f32x2(v.x);
        As2[(k0 + 1) * AST2 + r] = dup_f32x2(v.y);
        As2[(k0 + 2) * AST2 + r] = dup_f32x2(v.z);
        As2[(k0 + 3) * AST2 + r] = dup_f32x2(v.w);
    }
    // -- fill W tile ----------------------------------------------------------
    {
        const float4* W4 = (const float4*)W;
        float4* d4 = (float4*)Ws;
        #pragma unroll
        for (int i = 0; i < 8; i++) d4[tid + i * 512] = W4[tid + i * 512];
    }
    __syncthreads();

    const int rbase = (tid >> 4) * 4;      // 32 row-groups of 4
    const int cbase = (tid & 15) * 8;      // 16 col-groups of 8

    u64 acc[4][4];                          // [row][col-pair]
    #pragma unroll
    for (int r = 0; r < 4; r++)
        #pragma unroll
        for (int c = 0; c < 4; c++) acc[r][c] = 0ull;

    #pragma unroll 4
    for (int k = 0; k < 128; k++) {
        const u64* ap = As2 + k * AST2 + rbase;
        u64 a0 = ap[0], a1 = ap[1], a2 = ap[2], a3 = ap[3];   // broadcast LDS.64
        ulonglong2 wA = *(const ulonglong2*)(Ws + k * 128 + cbase);      // cols c..c+3
        ulonglong2 wB = *(const ulonglong2*)(Ws + k * 128 + cbase + 4);  // cols c+4..c+7
        ffma2(acc[0][0], a0, wA.x); ffma2(acc[0][1], a0, wA.y);
        ffma2(acc[0][2], a0, wB.x); ffma2(acc[0][3], a0, wB.y);
        ffma2(acc[1][0], a1, wA.x); ffma2(acc[1][1], a1, wA.y);
        ffma2(acc[1][2], a1, wB.x); ffma2(acc[1][3], a1, wB.y);
        ffma2(acc[2][0], a2, wA.x); ffma2(acc[2][1], a2, wA.y);
        ffma2(acc[2][2], a2, wB.x); ffma2(acc[2][3], a2, wB.y);
        ffma2(acc[3][0], a3, wA.x); ffma2(acc[3][1], a3, wA.y);
        ffma2(acc[3][2], a3, wB.x); ffma2(acc[3][3], a3, wB.y);
    }

    // -- epilogue --------------------------------------------------------------
    float bl[8];
    #pragma unroll
    for (int j = 0; j < 8; j++) bl[j] = bias ? bias[cbase + j] : 0.f;
    #pragma unroll
    for (int r = 0; r < 4; r++) {
        int gr = rowBlock + rbase + r;
        if (gr >= n) continue;
        F2U p0, p1, p2, p3;
        p0.u = acc[r][0]; p1.u = acc[r][1]; p2.u = acc[r][2]; p3.u = acc[r][3];
        float4 o0, o1;
        o0.x = p0.f.x + bl[0]; o0.y = p0.f.y + bl[1];
        o0.z = p1.f.x + bl[2]; o0.w = p1.f.y + bl[3];
        o1.x = p2.f.x + bl[4]; o1.y = p2.f.y + bl[5];
        o1.z = p3.f.x + bl[6]; o1.w = p3.f.y + bl[7];
        if (relu) {
            o0.x = fmaxf(o0.x, 0.f); o0.y = fmaxf(o0.y, 0.f);
            o0.z = fmaxf(o0.z, 0.f); o0.w = fmaxf(o0.w, 0.f);
            o1.x = fmaxf(o1.x, 0.f); o1.y = fmaxf(o1.y, 0.f);
            o1.z = fmaxf(o1.z, 0.f); o1.w = fmaxf(o1.w, 0.f);
        }
        float* dst = out + (size_t)gr * D + cbase;
        *(float4*)dst       = o0;
        *(float4*)(dst + 4) = o1;
    }
}

// ---------------- CSR gather aggregation -----------------------------------
__global__ void k_gather(const float* __restrict__ xw,
                         float* __restrict__ out,
                         const float* __restrict__ bias, int relu,
                         int n)
{
    int warp = (blockIdx.x * blockDim.x + threadIdx.x) >> 5;
    int lane = threadIdx.x & 31;
    if (warp >= n) return;
    const int d = warp;

    float dis = g_dis[d];
    float dis2 = dis * dis;
    float4 self = ((const float4*)(xw + (size_t)d * D))[lane];
    float4 acc;
    acc.x = self.x * dis2; acc.y = self.y * dis2;
    acc.z = self.z * dis2; acc.w = self.w * dis2;

    int e   = g_rowstart[d];
    int end = g_rowstart[d + 1];

    for (; e + 1 < end; e += 2) {
        int   s0 = g_csr_src[e],  s1 = g_csr_src[e + 1];
        float c0 = g_csr_coef[e], c1 = g_csr_coef[e + 1];
        float4 v0 = ((const float4*)(xw + (size_t)s0 * D))[lane];
        float4 v1 = ((const float4*)(xw + (size_t)s1 * D))[lane];
        acc.x = fmaf(c0, v0.x, acc.x); acc.y = fmaf(c0, v0.y, acc.y);
        acc.z = fmaf(c0, v0.z, acc.z); acc.w = fmaf(c0, v0.w, acc.w);
        acc.x = fmaf(c1, v1.x, acc.x); acc.y = fmaf(c1, v1.y, acc.y);
        acc.z = fmaf(c1, v1.z, acc.z); acc.w = fmaf(c1, v1.w, acc.w);
    }
    if (e < end) {
        int   s0 = g_csr_src[e];
        float c0 = g_csr_coef[e];
        float4 v0 = ((const float4*)(xw + (size_t)s0 * D))[lane];
        acc.x = fmaf(c0, v0.x, acc.x); acc.y = fmaf(c0, v0.y, acc.y);
        acc.z = fmaf(c0, v0.z, acc.z); acc.w = fmaf(c0, v0.w, acc.w);
    }

    const int col = lane * 4;
    acc.x += bias[col]; acc.y += bias[col + 1];
    acc.z += bias[col + 2]; acc.w += bias[col + 3];
    if (relu) {
        acc.x = fmaxf(acc.x, 0.f); acc.y = fmaxf(acc.y, 0.f);
        acc.z = fmaxf(acc.z, 0.f); acc.w = fmaxf(acc.w, 0.f);
    }
    ((float4*)(out + (size_t)d * D))[lane] = acc;
}

// ---------------- launch ---------------------------------------------------
extern "C" void kernel_launch(void* const* d_in, const int* in_sizes, int n_in,
                              void* d_out, int out_size)
{
    const float* x    = (const float*)d_in[0];
    const int*   edge = (const int*)d_in[1];   // int32 or int64 (detected)
    const float* W1 = (const float*)d_in[2]; const float* b1 = (const float*)d_in[3];
    const float* W2 = (const float*)d_in[4]; const float* b2 = (const float*)d_in[5];
    const float* Wv = (const float*)d_in[6]; const float* bv = (const float*)d_in[7];
    const float* Wt = (const float*)d_in[8]; const float* bt = (const float*)d_in[9];

    const int n = in_sizes[0] / D;
    const int E = in_sizes[1] / 2;

    float* out_h = (float*)d_out;
    float* out_v = out_h + (size_t)n * D;
    float* out_t = out_v + (size_t)n * D;

    float* xw = nullptr; cudaGetSymbolAddress((void**)&xw, g_xw);
    float* h  = nullptr; cudaGetSymbolAddress((void**)&h,  g_h);

    cudaFuncSetAttribute(k_gemm_p, cudaFuncAttributeMaxDynamicSharedMemorySize, GEMM_SMEM);

    const int TB = 256;
    const int nscan = (n + SCAN_BS - 1) / SCAN_BS;
    const int gemmGrid   = (n + GT - 1) / GT;
    const int gatherGrid = (n + 7) / 8;

    // launches 1-3 small so the conv1 GEMM is the 4th (ncu sample slot)
    k_detect<<<1, 512>>>(edge, 2 * E);
    k_zero_cnt<<<(n + TB - 1) / TB, TB>>>(n);
    k_zero_cur<<<(n + TB - 1) / TB, TB>>>(n);
    // 4: conv1 GEMM (+ folded degree histogram)
    k_gemm_p<<<gemmGrid, 512, GEMM_SMEM>>>(x, n, W1, nullptr, 0, xw, edge, E, 1);
    // normalization + CSR
    k_scan_block<<<nscan, SCAN_BS>>>(n);
    k_scan_tops<<<1, MAX_SCAN_BLOCKS>>>(nscan);
    k_scan_add<<<nscan, SCAN_BS>>>(n, E);
    k_fill<<<(E + TB - 1) / TB, TB>>>(edge, E);
    // conv1 aggregate -> h
    k_gather<<<gatherGrid, TB>>>(xw, h, b1, 1, n);
    // conv2
    k_gemm_p<<<gemmGrid, 512, GEMM_SMEM>>>(h, n, W2, nullptr, 0, xw,
                                           nullptr, 0, 0);
    k_gather<<<gatherGrid, TB>>>(xw, out_h, b2, 0, n);
    // heads
    k_gemm_p<<<gemmGrid, 512, GEMM_SMEM>>>(out_h, n, Wv, bv, 1, out_v,
                                           nullptr, 0, 0);
    k_gemm_p<<<gemmGrid, 512, GEMM_SMEM>>>(out_h, n, Wt, bt, 1, out_t,
                                           nullptr, 0, 0);
}

// round 10
// speedup vs baseline: 1.4788x; 1.4788x over previous
#include <cuda_runtime.h>

typedef unsigned long long u64;

#define MAXN 100000
#define MAXE 1600000
#define D    128
#define SCAN_BS 512
#define MAX_SCAN_BLOCKS 256

// conv GEMM: 256 rows x 128 cols, 512 threads
#define GTC 256
#define ATS_C 260                          // At stride (floats), mult of 4
#define AT_C_BYTES (128 * ATS_C * 4)       // 133120
#define WSTRIDE 140                        // skewed W stride (floats)
#define W_BYTES (128 * WSTRIDE * 4)        // 71680
#define SMEM_C (AT_C_BYTES + W_BYTES)      // 204800

// heads GEMM: 128 rows x 256 cols (two W), 512 threads
#define GTH 128
#define ATS_H 132
#define AT_H_BYTES (128 * ATS_H * 4)       // 67584
#define SMEM_H (AT_H_BYTES + 2 * W_BYTES)  // 210944

// ---------------- scratch (device globals; fully rewritten each launch) ----
__device__ __align__(16) float g_dis[MAXN];
__device__ __align__(16) float g_xw [(size_t)MAXN * D];
__device__ __align__(16) float g_h  [(size_t)MAXN * D];
__device__ int   g_cnt[MAXN];
__device__ int   g_incl[MAXN];
__device__ int   g_bsum[MAX_SCAN_BLOCKS];
__device__ int   g_rowstart[MAXN + 1];
__device__ int   g_cursor[MAXN];
__device__ __align__(16) int2 g_csr[MAXE];   // (src, coef-bits)
__device__ int g_is64;

// ---------------- edge dtype detection -------------------------------------
__global__ void k_detect(const int* __restrict__ e32, int nwords) {
    __shared__ int any;
    if (threadIdx.x == 0) any = 0;
    __syncthreads();
    int lim = nwords < 4096 ? nwords : 4096;
    for (int w = 1 + 2 * threadIdx.x; w < lim; w += 2 * blockDim.x)
        if (e32[w] != 0) any = 1;
    __syncthreads();
    if (threadIdx.x == 0) g_is64 = any ? 0 : 1;
}
__device__ __forceinline__ int edge_src(const int* e, int E, int i) {
    return g_is64 ? e[2 * (size_t)i] : e[i];
}
__device__ __forceinline__ int edge_dst(const int* e, int E, int i) {
    return g_is64 ? e[2 * ((size_t)E + i)] : e[(size_t)E + i];
}

// ---------------- zero (split so GEMM1 is the 4th launch for ncu) ----------
__global__ void k_zero_cnt(int n) {
    int i = blockIdx.x * blockDim.x + threadIdx.x;
    if (i < n) g_cnt[i] = 0;
}
__global__ void k_zero_cur(int n) {
    int i = blockIdx.x * blockDim.x + threadIdx.x;
    if (i < n) g_cursor[i] = 0;
}

// ---------------- CSR build -------------------------------------------------
__global__ void k_scan_block(int n) {
    __shared__ int sh[SCAN_BS];
    int i = blockIdx.x * SCAN_BS + threadIdx.x;
    int v = (i < n) ? g_cnt[i] : 0;
    if (i < n) g_dis[i] = rsqrtf((float)v + 1.0f);
    sh[threadIdx.x] = v;
    __syncthreads();
    #pragma unroll
    for (int off = 1; off < SCAN_BS; off <<= 1) {
        int t = (threadIdx.x >= off) ? sh[threadIdx.x - off] : 0;
        __syncthreads();
        sh[threadIdx.x] += t;
        __syncthreads();
    }
    if (i < n) g_incl[i] = sh[threadIdx.x];
    if (threadIdx.x == SCAN_BS - 1) g_bsum[blockIdx.x] = sh[threadIdx.x];
}
__global__ void k_scan_tops(int nblocks) {
    __shared__ int sh[MAX_SCAN_BLOCKS];
    int v = (threadIdx.x < nblocks) ? g_bsum[threadIdx.x] : 0;
    sh[threadIdx.x] = v;
    __syncthreads();
    #pragma unroll
    for (int off = 1; off < MAX_SCAN_BLOCKS; off <<= 1) {
        int t = (threadIdx.x >= off) ? sh[threadIdx.x - off] : 0;
        __syncthreads();
        sh[threadIdx.x] += t;
        __syncthreads();
    }
    g_bsum[threadIdx.x] = sh[threadIdx.x] - v;
}
__global__ void k_scan_add(int n, int E) {
    int i = blockIdx.x * SCAN_BS + threadIdx.x;
    if (i < n) {
        int excl = g_incl[i] - g_cnt[i] + g_bsum[blockIdx.x];
        g_rowstart[i] = excl;
        if (i == n - 1) g_rowstart[n] = excl + g_cnt[i];
    }
}
__global__ void k_fill(const int* __restrict__ edge, int E) {
    int i = blockIdx.x * blockDim.x + threadIdx.x;
    if (i < E) {
        int s = edge_src(edge, E, i);
        int d = edge_dst(edge, E, i);
        int pos = g_rowstart[d] + atomicAdd(&g_cursor[d], 1);
        g_csr[pos] = make_int2(s, __float_as_int(g_dis[s] * g_dis[d]));
    }
}

// ---------------- f32x2 helpers ---------------------------------------------
union F2U { float2 f; u64 u; };
__device__ __forceinline__ u64 dup_f32x2(float x) {
    F2U t; t.f = make_float2(x, x); return t.u;
}
__device__ __forceinline__ void ffma2(u64& acc, u64 a, u64 w) {
    asm("fma.rn.f32x2 %0, %1, %2, %0;" : "+l"(acc) : "l"(a), "l"(w));
}
// skewed W column mapping: spreads 8-col chunks across bank quads
__device__ __forceinline__ int wskew(int c) { return c + 4 * (c >> 5); }

// ---------------- conv GEMM: out = A @ W  (exact fp32 via FFMA2) ------------
// 256 rows x 128 cols x K=128, 512 threads, 8x8 thread tile.
// At[k][r] transposed, XOR-swizzled (4-way fill conflicts, 1-phase loads).
// Ws[k][wskew(c)] skewed (2-phase LDS.128 loads).
__global__ void __launch_bounds__(512, 1)
k_gemm_c(const float* __restrict__ A, int n,
         const float* __restrict__ W, float* __restrict__ out,
         const int* __restrict__ edge, int E, int hist)
{
    extern __shared__ __align__(16) char smem[];
    float* At = (float*)smem;                      // [128][ATS_C]
    float* Ws = (float*)(smem + AT_C_BYTES);       // [128][WSTRIDE] skewed

    const int tid = threadIdx.x;
    const int rowBlock = blockIdx.x * GTC;

    // folded degree histogram (fire-and-forget REDs)
    if (hist) {
        int per  = (E + gridDim.x - 1) / gridDim.x;
        int base = blockIdx.x * per;
        int lim  = base + per; if (lim > E) lim = E;
        for (int i = base + tid; i < lim; i += 512)
            atomicAdd(&g_cnt[edge_dst(edge, E, i)], 1);
    }

    // fill At (transposed + swizzled): At[k][r ^ ((k>>2&7)<<2)] = A[r][k]
    #pragma unroll
    for (int i = 0; i < 16; i++) {
        int idx = tid + i * 512;           // 8192: r=idx>>5 (0..255), c4=idx&31
        int r   = idx >> 5;
        int c4  = idx & 31;
        int grow = rowBlock + r;
        float4 v = make_float4(0.f, 0.f, 0.f, 0.f);
        if (grow < n) v = ((const float4*)(A + (size_t)grow * D))[c4];
        int rs = r ^ ((c4 & 7) << 2);      // swz(k)=((k>>2)&7)<<2, k=4c4+j
        int k0 = 4 * c4;
        At[(k0 + 0) * ATS_C + rs] = v.x;
        At[(k0 + 1) * ATS_C + rs] = v.y;
        At[(k0 + 2) * ATS_C + rs] = v.z;
        At[(k0 + 3) * ATS_C + rs] = v.w;
    }
    // fill Ws skewed: Ws[k][wskew(c)] = W[k][c]
    #pragma unroll
    for (int i = 0; i < 8; i++) {
        int idx = tid + i * 512;           // 4096 float4s: k=idx>>5, c4=idx&31
        int k   = idx >> 5;
        int c4  = idx & 31;
        float4 v = ((const float4*)(W + (size_t)k * D))[c4];
        *(float4*)(Ws + k * WSTRIDE + wskew(4 * c4)) = v;
    }
    __syncthreads();

    const int rbase = (tid >> 4) * 8;      // 32 rgroups of 8 rows
    const int cb    = wskew((tid & 15) * 8);  // skewed col base (contig 8)
    const int cbase = (tid & 15) * 8;

    u64 acc[8][4];
    #pragma unroll
    for (int r = 0; r < 8; r++)
        #pragma unroll
        for (int c = 0; c < 4; c++) acc[r][c] = 0ull;

    #pragma unroll 2
    for (int k4 = 0; k4 < 32; k4++) {
        int sw = (k4 & 7) << 2;
        int ra = rbase ^ sw;               // chunk holds logical rows rbase..+3
        int rb = (rbase + 4) ^ sw;         // logical rows rbase+4..+7
        #pragma unroll
        for (int j = 0; j < 4; j++) {
            int k = 4 * k4 + j;
            const float* atk = At + k * ATS_C;
            float4 a0 = *(const float4*)(atk + ra);
            float4 a1 = *(const float4*)(atk + rb);
            const float* wk = Ws + k * WSTRIDE + cb;
            ulonglong2 wA = *(const ulonglong2*)(wk);
            ulonglong2 wB = *(const ulonglong2*)(wk + 4);
            u64 ad[8];
            ad[0] = dup_f32x2(a0.x); ad[1] = dup_f32x2(a0.y);
            ad[2] = dup_f32x2(a0.z); ad[3] = dup_f32x2(a0.w);
            ad[4] = dup_f32x2(a1.x); ad[5] = dup_f32x2(a1.y);
            ad[6] = dup_f32x2(a1.z); ad[7] = dup_f32x2(a1.w);
            #pragma unroll
            for (int r = 0; r < 8; r++) {
                ffma2(acc[r][0], ad[r], wA.x);
                ffma2(acc[r][1], ad[r], wA.y);
                ffma2(acc[r][2], ad[r], wB.x);
                ffma2(acc[r][3], ad[r], wB.y);
            }
        }
    }

    #pragma unroll
    for (int r = 0; r < 8; r++) {
        int gr = rowBlock + rbase + r;
        if (gr >= n) continue;
        F2U p0, p1, p2, p3;
        p0.u = acc[r][0]; p1.u = acc[r][1]; p2.u = acc[r][2]; p3.u = acc[r][3];
        float4 o0 = make_float4(p0.f.x, p0.f.y, p1.f.x, p1.f.y);
        float4 o1 = make_float4(p2.f.x, p2.f.y, p3.f.x, p3.f.y);
        float* dst = out + (size_t)gr * D + cbase;
        *(float4*)dst       = o0;
        *(float4*)(dst + 4) = o1;
    }
}

// ---------------- heads GEMM: out_v/out_t = relu(A@Wv+bv / A@Wt+bt) ---------
// 128 rows x 256 cols (two 128-col W), 512 threads, 8x8 tile.
__global__ void __launch_bounds__(512, 1)
k_gemm_h(const float* __restrict__ A, int n,
         const float* __restrict__ Wv, const float* __restrict__ bv,
         float* __restrict__ outv,
         const float* __restrict__ Wt, const float* __restrict__ bt,
         float* __restrict__ outt)
{
    extern __shared__ __align__(16) char smem[];
    float* At = (float*)smem;                        // [128][ATS_H]
    float* Ws = (float*)(smem + AT_H_BYTES);         // [2][128][WSTRIDE]

    const int tid = threadIdx.x;
    const int rowBlock = blockIdx.x * GTH;

    #pragma unroll
    for (int i = 0; i < 8; i++) {
        int idx = tid + i * 512;           // 4096: r=idx>>5 (0..127), c4
        int r   = idx >> 5;
        int c4  = idx & 31;
        int grow = rowBlock + r;
        float4 v = make_float4(0.f, 0.f, 0.f, 0.f);
        if (grow < n) v = ((const float4*)(A + (size_t)grow * D))[c4];
        int rs = r ^ ((c4 & 7) << 2);
        int k0 = 4 * c4;
        At[(k0 + 0) * ATS_H + rs] = v.x;
        At[(k0 + 1) * ATS_H + rs] = v.y;
        At[(k0 + 2) * ATS_H + rs] = v.z;
        At[(k0 + 3) * ATS_H + rs] = v.w;
    }
    #pragma unroll
    for (int i = 0; i < 16; i++) {
        int idx = tid + i * 512;           // 8192: half=idx>=4096
        int half = idx >> 12;
        int j    = idx & 4095;
        int k    = j >> 5;
        int c4   = j & 31;
        const float* W = half ? Wt : Wv;
        float4 v = ((const float4*)(W + (size_t)k * D))[c4];
        *(float4*)(Ws + half * (W_BYTES / 4) + k * WSTRIDE + wskew(4 * c4)) = v;
    }
    __syncthreads();

    const int rbase = (tid >> 5) * 8;       // warp -> 8 rows (broadcast A)
    const int cgrp  = tid & 31;             // 32 col-groups over 256 cols
    const int head  = cgrp >> 4;
    const int cc    = (cgrp & 15) * 8;
    const float* Wsh = Ws + head * (W_BYTES / 4);
    const int cb = wskew(cc);

    u64 acc[8][4];
    #pragma unroll
    for (int r = 0; r < 8; r++)
        #pragma unroll
        for (int c = 0; c < 4; c++) acc[r][c] = 0ull;

    #pragma unroll 2
    for (int k4 = 0; k4 < 32; k4++) {
        int sw = (k4 & 7) << 2;
        int ra = rbase ^ sw;
        int rb = (rbase + 4) ^ sw;
        #pragma unroll
        for (int j = 0; j < 4; j++) {
            int k = 4 * k4 + j;
            const float* atk = At + k * ATS_H;
            float4 a0 = *(const float4*)(atk + ra);
            float4 a1 = *(const float4*)(atk + rb);
            const float* wk = Wsh + k * WSTRIDE + cb;
            ulonglong2 wA = *(const ulonglong2*)(wk);
            ulonglong2 wB = *(const ulonglong2*)(wk + 4);
            u64 ad[8];
            ad[0] = dup_f32x2(a0.x); ad[1] = dup_f32x2(a0.y);
            ad[2] = dup_f32x2(a0.z); ad[3] = dup_f32x2(a0.w);
            ad[4] = dup_f32x2(a1.x); ad[5] = dup_f32x2(a1.y);
            ad[6] = dup_f32x2(a1.z); ad[7] = dup_f32x2(a1.w);
            #pragma unroll
            for (int r = 0; r < 8; r++) {
                ffma2(acc[r][0], ad[r], wA.x);
                ffma2(acc[r][1], ad[r], wA.y);
                ffma2(acc[r][2], ad[r], wB.x);
                ffma2(acc[r][3], ad[r], wB.y);
            }
        }
    }

    const float* bias = head ? bt : bv;
    float*       out  = head ? outt : outv;
    float b[8];
    #pragma unroll
    for (int j = 0; j < 8; j++) b[j] = bias[cc + j];
    #pragma unroll
    for (int r = 0; r < 8; r++) {
        int gr = rowBlock + rbase + r;
        if (gr >= n) continue;
        F2U p0, p1, p2, p3;
        p0.u = acc[r][0]; p1.u = acc[r][1]; p2.u = acc[r][2]; p3.u = acc[r][3];
        float4 o0, o1;
        o0.x = fmaxf(p0.f.x + b[0], 0.f); o0.y = fmaxf(p0.f.y + b[1], 0.f);
        o0.z = fmaxf(p1.f.x + b[2], 0.f); o0.w = fmaxf(p1.f.y + b[3], 0.f);
        o1.x = fmaxf(p2.f.x + b[4], 0.f); o1.y = fmaxf(p2.f.y + b[5], 0.f);
        o1.z = fmaxf(p3.f.x + b[6], 0.f); o1.w = fmaxf(p3.f.y + b[7], 0.f);
        float* dst = out + (size_t)gr * D + cc;
        *(float4*)dst       = o0;
        *(float4*)(dst + 4) = o1;
    }
}

// ---------------- CSR gather aggregation -----------------------------------
__global__ void k_gather(const float* __restrict__ xw,
                         float* __restrict__ out,
                         const float* __restrict__ bias, int relu,
                         int n)
{
    int warp = (blockIdx.x * blockDim.x + threadIdx.x) >> 5;
    int lane = threadIdx.x & 31;
    if (warp >= n) return;
    const int d = warp;

    float dis = g_dis[d];
    float dis2 = dis * dis;
    float4 self = ((const float4*)(xw + (size_t)d * D))[lane];
    float4 acc;
    acc.x = self.x * dis2; acc.y = self.y * dis2;
    acc.z = self.z * dis2; acc.w = self.w * dis2;

    int e   = g_rowstart[d];
    int end = g_rowstart[d + 1];

    for (; e + 1 < end; e += 2) {
        int2 e0 = g_csr[e];
        int2 e1 = g_csr[e + 1];
        float c0 = __int_as_float(e0.y);
        float c1 = __int_as_float(e1.y);
        float4 v0 = ((const float4*)(xw + (size_t)e0.x * D))[lane];
        float4 v1 = ((const float4*)(xw + (size_t)e1.x * D))[lane];
        acc.x = fmaf(c0, v0.x, acc.x); acc.y = fmaf(c0, v0.y, acc.y);
        acc.z = fmaf(c0, v0.z, acc.z); acc.w = fmaf(c0, v0.w, acc.w);
        acc.x = fmaf(c1, v1.x, acc.x); acc.y = fmaf(c1, v1.y, acc.y);
        acc.z = fmaf(c1, v1.z, acc.z); acc.w = fmaf(c1, v1.w, acc.w);
    }
    if (e < end) {
        int2 e0 = g_csr[e];
        float c0 = __int_as_float(e0.y);
        float4 v0 = ((const float4*)(xw + (size_t)e0.x * D))[lane];
        acc.x = fmaf(c0, v0.x, acc.x); acc.y = fmaf(c0, v0.y, acc.y);
        acc.z = fmaf(c0, v0.z, acc.z); acc.w = fmaf(c0, v0.w, acc.w);
    }

    const int col = lane * 4;
    acc.x += bias[col]; acc.y += bias[col + 1];
    acc.z += bias[col + 2]; acc.w += bias[col + 3];
    if (relu) {
        acc.x = fmaxf(acc.x, 0.f); acc.y = fmaxf(acc.y, 0.f);
        acc.z = fmaxf(acc.z, 0.f); acc.w = fmaxf(acc.w, 0.f);
    }
    ((float4*)(out + (size_t)d * D))[lane] = acc;
}

// ---------------- launch ---------------------------------------------------
extern "C" void kernel_launch(void* const* d_in, const int* in_sizes, int n_in,
                              void* d_out, int out_size)
{
    const float* x    = (const float*)d_in[0];
    const int*   edge = (const int*)d_in[1];   // int32 or int64 (detected)
    const float* W1 = (const float*)d_in[2]; const float* b1 = (const float*)d_in[3];
    const float* W2 = (const float*)d_in[4]; const float* b2 = (const float*)d_in[5];
    const float* Wv = (const float*)d_in[6]; const float* bv = (const float*)d_in[7];
    const float* Wt = (const float*)d_in[8]; const float* bt = (const float*)d_in[9];

    const int n = in_sizes[0] / D;
    const int E = in_sizes[1] / 2;

    float* out_h = (float*)d_out;
    float* out_v = out_h + (size_t)n * D;
    float* out_t = out_v + (size_t)n * D;

    float* xw = nullptr; cudaGetSymbolAddress((void**)&xw, g_xw);
    float* h  = nullptr; cudaGetSymbolAddress((void**)&h,  g_h);

    cudaFuncSetAttribute(k_gemm_c, cudaFuncAttributeMaxDynamicSharedMemorySize, SMEM_C);
    cudaFuncSetAttribute(k_gemm_h, cudaFuncAttributeMaxDynamicSharedMemorySize, SMEM_H);

    const int TB = 256;
    const int nscan = (n + SCAN_BS - 1) / SCAN_BS;
    const int convGrid   = (n + GTC - 1) / GTC;
    const int headGrid   = (n + GTH - 1) / GTH;
    const int gatherGrid = (n + 7) / 8;

    // launches 1-3 small so the conv1 GEMM is the 4th (ncu sample slot)
    k_detect<<<1, 512>>>(edge, 2 * E);
    k_zero_cnt<<<(n + TB - 1) / TB, TB>>>(n);
    k_zero_cur<<<(n + TB - 1) / TB, TB>>>(n);
    // 4: conv1 GEMM (+ folded degree histogram)
    k_gemm_c<<<convGrid, 512, SMEM_C>>>(x, n, W1, xw, edge, E, 1);
    // normalization + CSR
    k_scan_block<<<nscan, SCAN_BS>>>(n);
    k_scan_tops<<<1, MAX_SCAN_BLOCKS>>>(nscan);
    k_scan_add<<<nscan, SCAN_BS>>>(n, E);
    k_fill<<<(E + TB - 1) / TB, TB>>>(edge, E);
    // conv1 aggregate -> h
    k_gather<<<gatherGrid, TB>>>(xw, h, b1, 1, n);
    // conv2
    k_gemm_c<<<convGrid, 512, SMEM_C>>>(h, n, W2, xw, nullptr, 0, 0);
    k_gather<<<gatherGrid, TB>>>(xw, out_h, b2, 0, n);
    // heads: one launch, both W
    k_gemm_h<<<headGrid, 512, SMEM_H>>>(out_h, n, Wv, bv, out_v, Wt, bt, out_t);
}